// round 8
// baseline (speedup 1.0000x reference)
#include <cuda_runtime.h>

// BlockDiagonalLinearAlignment on GB300 (sm_103a)
// Warp-per-row, all-blocks-densified weights in registers, fp32x2 packed math,
// persistent grid. Memory-bound target ~40-45us.

#define GRID_CTAS 296          // 2 CTAs/SM * 148 SMs
#define CTA_THREADS 256
#define TOTAL_WARPS (GRID_CTAS * CTA_THREADS / 32)   // 2368

__device__ __forceinline__ unsigned long long pk2(float a, float b) {
    unsigned long long r;
    asm("mov.b64 %0, {%1, %2};" : "=l"(r) : "f"(a), "f"(b));
    return r;
}
__device__ __forceinline__ void up2(unsigned long long v, float& a, float& b) {
    asm("mov.b64 {%0, %1}, %2;" : "=f"(a), "=f"(b) : "l"(v));
}
__device__ __forceinline__ unsigned long long fma2(unsigned long long a,
                                                   unsigned long long b,
                                                   unsigned long long c) {
    unsigned long long d;
    asm("fma.rn.f32x2 %0, %1, %2, %3;" : "=l"(d) : "l"(a), "l"(b), "l"(c));
    return d;
}
__device__ __forceinline__ unsigned long long mul2(unsigned long long a,
                                                   unsigned long long b) {
    unsigned long long d;
    asm("mul.rn.f32x2 %0, %1, %2;" : "=l"(d) : "l"(a), "l"(b));
    return d;
}

__device__ __forceinline__ float4 shflx4(float4 v, int m) {
    float4 r;
    r.x = __shfl_xor_sync(0xffffffffu, v.x, m);
    r.y = __shfl_xor_sync(0xffffffffu, v.y, m);
    r.z = __shfl_xor_sync(0xffffffffu, v.z, m);
    r.w = __shfl_xor_sync(0xffffffffu, v.w, m);
    return r;
}

// Densified weight W_all[k][o][d] from the raw inputs.
// DENSE blocks k in {0,3,6}: W_dense[k/3][o][d]           (torch Linear: y = x @ W^T)
// DIAG  blocks k in {1,4,7}: (o==d) ? s_diag[(k-1)/3][o] : 0
// LR    blocks k in {2,5}  : sum_r U[(k-2)/3][o][r] * V[(k-2)/3][d][r]
__device__ __forceinline__ float wval(int k, int o, int d,
                                      const float* __restrict__ Wd,
                                      const float* __restrict__ sd,
                                      const float* __restrict__ U,
                                      const float* __restrict__ V) {
    if (k == 0 || k == 3 || k == 6) {
        return Wd[(k / 3) * 256 + o * 16 + d];
    } else if (k == 2 || k == 5) {
        const float* Uj = U + ((k - 2) / 3) * 64 + o * 4;
        const float* Vj = V + ((k - 2) / 3) * 64 + d * 4;
        return Uj[0] * Vj[0] + Uj[1] * Vj[1] + Uj[2] * Vj[2] + Uj[3] * Vj[3];
    } else {
        return (d == o) ? sd[((k - 1) / 3) * 16 + o] : 0.0f;
    }
}

__global__ void __launch_bounds__(CTA_THREADS, 2)
bdla_kernel(const float4* __restrict__ x,
            const float* __restrict__ Wd,
            const float* __restrict__ sd,
            const float* __restrict__ U,
            const float* __restrict__ V,
            float4* __restrict__ y,
            int nrows) {
    const int lane = threadIdx.x & 31;
    const int gw = (int)((blockIdx.x * blockDim.x + threadIdx.x) >> 5);
    const int k = lane >> 2;   // block id 0..7
    const int q = lane & 3;    // quarter within block (outputs 4q..4q+3)

    // ---- Build this thread's weight slab in registers (once per ~110 rows).
    // pwA[t] = (W[k][4q+0][d_t], W[k][4q+1][d_t])
    // pwB[t] = (W[k][4q+2][d_t], W[k][4q+3][d_t])
    // d_t ordering matches the shuffle-gather chunk order: chunk(q^cc), cc=0..3.
    unsigned long long pwA[16], pwB[16];
    {
        const int oA0 = 4 * q, oA1 = 4 * q + 1, oB0 = 4 * q + 2, oB1 = 4 * q + 3;
#pragma unroll
        for (int cc = 0; cc < 4; ++cc) {
            const int ch = q ^ cc;
#pragma unroll
            for (int i = 0; i < 4; ++i) {
                const int d = ch * 4 + i;
                const float a0 = wval(k, oA0, d, Wd, sd, U, V);
                const float a1 = wval(k, oA1, d, Wd, sd, U, V);
                const float b0 = wval(k, oB0, d, Wd, sd, U, V);
                const float b1 = wval(k, oB1, d, Wd, sd, U, V);
                pwA[cc * 4 + i] = pk2(a0, a1);
                pwB[cc * 4 + i] = pk2(b0, b1);
            }
        }
    }

    const int stride = TOTAL_WARPS;
    int r = gw;

    const float4 fzero = make_float4(0.f, 0.f, 0.f, 0.f);
    float4 v0 = (r < nrows) ? x[(unsigned)r * 32u + lane] : fzero;
    float4 v1 = (r + stride < nrows) ? x[(unsigned)(r + stride) * 32u + lane] : fzero;

    auto process = [&](float4 v, int row) {
        // Gather full 16-float block input across the 4-lane group.
        // v = chunk q, c1 = chunk q^1, c2 = chunk q^2, c3 = chunk q^3
        float4 c1 = shflx4(v, 1);
        float4 c2 = shflx4(v, 2);
        float4 c3 = shflx4(c1, 2);

        unsigned long long accA = 0ull, accB = 0ull;  // (0.f,0.f) bit pattern
#pragma unroll
        for (int t = 0; t < 16; ++t) {
            const int cc = t >> 2, i = t & 3;
            float4 c = (cc == 0) ? v : (cc == 1) ? c1 : (cc == 2) ? c2 : c3;
            float xv = (i == 0) ? c.x : (i == 1) ? c.y : (i == 2) ? c.z : c.w;
            unsigned long long b = pk2(xv, xv);
            accA = fma2(b, pwA[t], accA);
            accB = fma2(b, pwB[t], accB);
        }

        // Sum of squares of this lane's 4 outputs, packed.
        unsigned long long s2 = fma2(accB, accB, fma2(accA, accA, 0ull));
        float s0, s1;
        up2(s2, s0, s1);
        float ssq = s0 + s1;
        // Full-warp butterfly: row norm.
#pragma unroll
        for (int m = 16; m > 0; m >>= 1)
            ssq += __shfl_xor_sync(0xffffffffu, ssq, m);

        const float sc = __fdividef(1.0f, sqrtf(ssq) + 1e-8f);
        const unsigned long long pc = pk2(sc, sc);
        const unsigned long long ra = mul2(accA, pc);
        const unsigned long long rb = mul2(accB, pc);
        float4 o;
        up2(ra, o.x, o.y);
        up2(rb, o.z, o.w);
        // lane == 4k+q == float4 index of this lane's outputs within the row
        y[(unsigned)row * 32u + lane] = o;
    };

    while (r < nrows) {
        const int r2 = r + 2 * stride;
        const int r3 = r + 3 * stride;
        float4 n0 = (r2 < nrows) ? x[(unsigned)r2 * 32u + lane] : fzero;
        float4 n1 = (r3 < nrows) ? x[(unsigned)r3 * 32u + lane] : fzero;

        process(v0, r);
        if (r + stride < nrows) process(v1, r + stride);

        v0 = n0;
        v1 = n1;
        r = r2;
    }
}

extern "C" void kernel_launch(void* const* d_in, const int* in_sizes, int n_in,
                              void* d_out, int out_size) {
    const float4* x = (const float4*)d_in[0];
    const float* Wd = (const float*)d_in[1];
    const float* sd = (const float*)d_in[2];
    const float* U = (const float*)d_in[3];
    const float* V = (const float*)d_in[4];
    float4* y = (float4*)d_out;
    const int nrows = in_sizes[0] >> 7;  // elements / 128

    bdla_kernel<<<GRID_CTAS, CTA_THREADS>>>(x, Wd, sd, U, V, y, nrows);
}

// round 12
// speedup vs baseline: 1.1164x; 1.1164x over previous
#include <cuda_runtime.h>

// BlockDiagonalLinearAlignment on GB300 (sm_103a)
// Warp-per-row, densified per-lane register weights, fp32x2 packed math,
// persistent grid, depth-4 software pipeline (R8: was depth-2; kernel was
// latency-bound at DRAM=40.8%, occ=23.7%).

#define GRID_CTAS 296          // 2 CTAs/SM * 148 SMs
#define CTA_THREADS 256
#define TOTAL_WARPS (GRID_CTAS * CTA_THREADS / 32)   // 2368

__device__ __forceinline__ unsigned long long pk2(float a, float b) {
    unsigned long long r;
    asm("mov.b64 %0, {%1, %2};" : "=l"(r) : "f"(a), "f"(b));
    return r;
}
__device__ __forceinline__ void up2(unsigned long long v, float& a, float& b) {
    asm("mov.b64 {%0, %1}, %2;" : "=f"(a), "=f"(b) : "l"(v));
}
__device__ __forceinline__ unsigned long long fma2(unsigned long long a,
                                                   unsigned long long b,
                                                   unsigned long long c) {
    unsigned long long d;
    asm("fma.rn.f32x2 %0, %1, %2, %3;" : "=l"(d) : "l"(a), "l"(b), "l"(c));
    return d;
}
__device__ __forceinline__ unsigned long long mul2(unsigned long long a,
                                                   unsigned long long b) {
    unsigned long long d;
    asm("mul.rn.f32x2 %0, %1, %2;" : "=l"(d) : "l"(a), "l"(b));
    return d;
}

__device__ __forceinline__ float4 shflx4(float4 v, int m) {
    float4 r;
    r.x = __shfl_xor_sync(0xffffffffu, v.x, m);
    r.y = __shfl_xor_sync(0xffffffffu, v.y, m);
    r.z = __shfl_xor_sync(0xffffffffu, v.z, m);
    r.w = __shfl_xor_sync(0xffffffffu, v.w, m);
    return r;
}

// Densified weight W_all[k][o][d] from the raw inputs.
// DENSE blocks k in {0,3,6}: W_dense[k/3][o][d]           (torch Linear: y = x @ W^T)
// DIAG  blocks k in {1,4,7}: (o==d) ? s_diag[(k-1)/3][o] : 0
// LR    blocks k in {2,5}  : sum_r U[(k-2)/3][o][r] * V[(k-2)/3][d][r]
__device__ __forceinline__ float wval(int k, int o, int d,
                                      const float* __restrict__ Wd,
                                      const float* __restrict__ sd,
                                      const float* __restrict__ U,
                                      const float* __restrict__ V) {
    if (k == 0 || k == 3 || k == 6) {
        return Wd[(k / 3) * 256 + o * 16 + d];
    } else if (k == 2 || k == 5) {
        const float* Uj = U + ((k - 2) / 3) * 64 + o * 4;
        const float* Vj = V + ((k - 2) / 3) * 64 + d * 4;
        return Uj[0] * Vj[0] + Uj[1] * Vj[1] + Uj[2] * Vj[2] + Uj[3] * Vj[3];
    } else {
        return (d == o) ? sd[((k - 1) / 3) * 16 + o] : 0.0f;
    }
}

__global__ void __launch_bounds__(CTA_THREADS, 2)
bdla_kernel(const float4* __restrict__ x,
            const float* __restrict__ Wd,
            const float* __restrict__ sd,
            const float* __restrict__ U,
            const float* __restrict__ V,
            float4* __restrict__ y,
            int nrows) {
    const int lane = threadIdx.x & 31;
    const int gw = (int)((blockIdx.x * blockDim.x + threadIdx.x) >> 5);
    const int k = lane >> 2;   // block id 0..7
    const int q = lane & 3;    // quarter within block (outputs 4q..4q+3)

    // ---- Per-lane weight slab in registers (built once per ~110 rows).
    // pwA[t] = (W[k][4q+0][d_t], W[k][4q+1][d_t])
    // pwB[t] = (W[k][4q+2][d_t], W[k][4q+3][d_t])
    // d_t ordering matches the shuffle-gather chunk order: chunk(q^cc), cc=0..3.
    unsigned long long pwA[16], pwB[16];
    {
        const int oA0 = 4 * q, oA1 = 4 * q + 1, oB0 = 4 * q + 2, oB1 = 4 * q + 3;
#pragma unroll
        for (int cc = 0; cc < 4; ++cc) {
            const int ch = q ^ cc;
#pragma unroll
            for (int i = 0; i < 4; ++i) {
                const int d = ch * 4 + i;
                const float a0 = wval(k, oA0, d, Wd, sd, U, V);
                const float a1 = wval(k, oA1, d, Wd, sd, U, V);
                const float b0 = wval(k, oB0, d, Wd, sd, U, V);
                const float b1 = wval(k, oB1, d, Wd, sd, U, V);
                pwA[cc * 4 + i] = pk2(a0, a1);
                pwB[cc * 4 + i] = pk2(b0, b1);
            }
        }
    }

    const int stride = TOTAL_WARPS;
    int r = gw;

    const float4 fzero = make_float4(0.f, 0.f, 0.f, 0.f);
    // Depth-4 pipeline: 4 rows in flight per warp.
    float4 v0 = (r              < nrows) ? x[(unsigned)r * 32u + lane] : fzero;
    float4 v1 = (r +     stride < nrows) ? x[(unsigned)(r +     stride) * 32u + lane] : fzero;
    float4 v2 = (r + 2 * stride < nrows) ? x[(unsigned)(r + 2 * stride) * 32u + lane] : fzero;
    float4 v3 = (r + 3 * stride < nrows) ? x[(unsigned)(r + 3 * stride) * 32u + lane] : fzero;

    auto process = [&](float4 v, int row) {
        // Gather full 16-float block input across the 4-lane group.
        // v = chunk q, c1 = chunk q^1, c2 = chunk q^2, c3 = chunk q^3
        float4 c1 = shflx4(v, 1);
        float4 c2 = shflx4(v, 2);
        float4 c3 = shflx4(c1, 2);

        unsigned long long accA = 0ull, accB = 0ull;  // (0.f,0.f) bit pattern
#pragma unroll
        for (int t = 0; t < 16; ++t) {
            const int cc = t >> 2, i = t & 3;
            float4 c = (cc == 0) ? v : (cc == 1) ? c1 : (cc == 2) ? c2 : c3;
            float xv = (i == 0) ? c.x : (i == 1) ? c.y : (i == 2) ? c.z : c.w;
            unsigned long long b = pk2(xv, xv);
            accA = fma2(b, pwA[t], accA);
            accB = fma2(b, pwB[t], accB);
        }

        // Sum of squares of this lane's 4 outputs, packed.
        unsigned long long s2 = fma2(accB, accB, fma2(accA, accA, 0ull));
        float s0, s1;
        up2(s2, s0, s1);
        float ssq = s0 + s1;
        // Full-warp butterfly: row norm.
#pragma unroll
        for (int m = 16; m > 0; m >>= 1)
            ssq += __shfl_xor_sync(0xffffffffu, ssq, m);

        const float sc = __fdividef(1.0f, sqrtf(ssq) + 1e-8f);
        const unsigned long long pc = pk2(sc, sc);
        const unsigned long long ra = mul2(accA, pc);
        const unsigned long long rb = mul2(accB, pc);
        float4 o;
        up2(ra, o.x, o.y);
        up2(rb, o.z, o.w);
        // lane == 4k+q == float4 index of this lane's outputs within the row
        y[(unsigned)row * 32u + lane] = o;
    };

    while (r < nrows) {
        const int rn = r + 4 * stride;
        // Issue next wave of loads before consuming the current one (MLP=4).
        float4 n0 = (rn              < nrows) ? x[(unsigned)rn * 32u + lane] : fzero;
        float4 n1 = (rn +     stride < nrows) ? x[(unsigned)(rn +     stride) * 32u + lane] : fzero;
        float4 n2 = (rn + 2 * stride < nrows) ? x[(unsigned)(rn + 2 * stride) * 32u + lane] : fzero;
        float4 n3 = (rn + 3 * stride < nrows) ? x[(unsigned)(rn + 3 * stride) * 32u + lane] : fzero;

        process(v0, r);
        if (r +     stride < nrows) process(v1, r +     stride);
        if (r + 2 * stride < nrows) process(v2, r + 2 * stride);
        if (r + 3 * stride < nrows) process(v3, r + 3 * stride);

        v0 = n0; v1 = n1; v2 = n2; v3 = n3;
        r = rn;
    }
}

extern "C" void kernel_launch(void* const* d_in, const int* in_sizes, int n_in,
                              void* d_out, int out_size) {
    const float4* x = (const float4*)d_in[0];
    const float* Wd = (const float*)d_in[1];
    const float* sd = (const float*)d_in[2];
    const float* U = (const float*)d_in[3];
    const float* V = (const float*)d_in[4];
    float4* y = (float4*)d_out;
    const int nrows = in_sizes[0] >> 7;  // elements / 128

    bdla_kernel<<<GRID_CTAS, CTA_THREADS>>>(x, Wd, sd, U, V, y, nrows);
}